// round 1
// baseline (speedup 1.0000x reference)
#include <cuda_runtime.h>
#include <math.h>

// Problem constants
#define BB 2
#define SS 2048
#define DD 1024
#define HH 16
#define DK 64
#define MROWS (BB * SS)   // 4096

// ---------------- scratch (static device globals; no allocation allowed) ----
__device__ float g_Q[BB * SS * DD];
__device__ float g_K[BB * SS * DD];
__device__ float g_V[BB * SS * DD];
__device__ float g_AO[BB * SS * DD];

// ---------------- GEMM: C = A * W^T + bias -----------------------------
// A: (M,K) row-major, W: (N,K) row-major, C: (M,N) row-major.
// Block tile 128x128, BK=16, 256 threads, 8x8 per thread.
#define BM 128
#define BN 128
#define BK 16

__global__ __launch_bounds__(256) void gemm_bias_kernel(
    const float* __restrict__ A, const float* __restrict__ W,
    const float* __restrict__ bias, float* __restrict__ C,
    int M, int N, int K)
{
    __shared__ float As[BK][BM];
    __shared__ float Ws[BK][BN];

    const int tid = threadIdx.x;
    const int tx = tid & 15;        // 0..15
    const int ty = tid >> 4;        // 0..15
    const int bm = blockIdx.y * BM;
    const int bn = blockIdx.x * BN;

    float acc[8][8];
#pragma unroll
    for (int i = 0; i < 8; i++)
#pragma unroll
        for (int j = 0; j < 8; j++) acc[i][j] = 0.f;

    for (int k0 = 0; k0 < K; k0 += BK) {
        // load 128x16 tiles of A and W, store transposed (k-major) in smem
#pragma unroll
        for (int t = 0; t < 2; t++) {
            int f = tid + t * 256;          // 0..511 (float4 index)
            int row = f >> 2;               // 0..127
            int kq = f & 3;                 // 0..3
            float4 a = *(const float4*)&A[(long)(bm + row) * K + k0 + kq * 4];
            As[kq * 4 + 0][row] = a.x;
            As[kq * 4 + 1][row] = a.y;
            As[kq * 4 + 2][row] = a.z;
            As[kq * 4 + 3][row] = a.w;
            float4 w = *(const float4*)&W[(long)(bn + row) * K + k0 + kq * 4];
            Ws[kq * 4 + 0][row] = w.x;
            Ws[kq * 4 + 1][row] = w.y;
            Ws[kq * 4 + 2][row] = w.z;
            Ws[kq * 4 + 3][row] = w.w;
        }
        __syncthreads();

#pragma unroll
        for (int kk = 0; kk < BK; kk++) {
            float ar[8], wr[8];
            float4 a0 = *(const float4*)&As[kk][ty * 8];
            float4 a1 = *(const float4*)&As[kk][ty * 8 + 4];
            ar[0] = a0.x; ar[1] = a0.y; ar[2] = a0.z; ar[3] = a0.w;
            ar[4] = a1.x; ar[5] = a1.y; ar[6] = a1.z; ar[7] = a1.w;
            float4 w0 = *(const float4*)&Ws[kk][tx * 8];
            float4 w1 = *(const float4*)&Ws[kk][tx * 8 + 4];
            wr[0] = w0.x; wr[1] = w0.y; wr[2] = w0.z; wr[3] = w0.w;
            wr[4] = w1.x; wr[5] = w1.y; wr[6] = w1.z; wr[7] = w1.w;
#pragma unroll
            for (int i = 0; i < 8; i++)
#pragma unroll
                for (int j = 0; j < 8; j++)
                    acc[i][j] = fmaf(ar[i], wr[j], acc[i][j]);
        }
        __syncthreads();
    }

    // epilogue: + bias, write
    float bj[8];
#pragma unroll
    for (int j = 0; j < 8; j++) bj[j] = bias[bn + tx * 8 + j];
#pragma unroll
    for (int i = 0; i < 8; i++) {
        long r = bm + ty * 8 + i;
        float4 o0, o1;
        o0.x = acc[i][0] + bj[0]; o0.y = acc[i][1] + bj[1];
        o0.z = acc[i][2] + bj[2]; o0.w = acc[i][3] + bj[3];
        o1.x = acc[i][4] + bj[4]; o1.y = acc[i][5] + bj[5];
        o1.z = acc[i][6] + bj[6]; o1.w = acc[i][7] + bj[7];
        *(float4*)&C[r * N + bn + tx * 8] = o0;
        *(float4*)&C[r * N + bn + tx * 8 + 4] = o1;
    }
}

// ---------------- Flash attention (causal), fp32 -------------------------
// grid: (S/64, B*H), block 256 threads (16x16 -> 4x4 per thread tiles)
__global__ __launch_bounds__(256) void attn_kernel(
    const float* __restrict__ Qp, const float* __restrict__ Kp,
    const float* __restrict__ Vp, float* __restrict__ AO)
{
    __shared__ float Qs[64][64];   // natural [q][k]
    __shared__ float KVs[64][64];  // K transposed [k][c], then V natural [c][d]
    __shared__ float Ps[64][64];   // probs [q][c]

    const int tid = threadIdx.x;
    const int tx = tid & 15;
    const int ty = tid >> 4;
    const int bh = blockIdx.y;
    const int b = bh / HH;
    const int h = bh % HH;
    const int qt = blockIdx.x;
    const float scale = 0.125f;   // 1/sqrt(64)

    const long head_off = (long)h * DK;
    const long bq_base = ((long)b * SS + qt * 64) * DD + head_off;

    // load Q tile (64 x 64), rows stride DD
    for (int f = tid; f < 64 * 16; f += 256) {   // float4 index
        int r = f >> 4;          // 0..63
        int c4 = f & 15;         // 0..15
        *(float4*)&Qs[r][c4 * 4] = *(const float4*)&Qp[bq_base + (long)r * DD + c4 * 4];
    }

    float m[4], l[4], acc[4][4];
#pragma unroll
    for (int i = 0; i < 4; i++) {
        m[i] = -3.0e38f; l[i] = 0.f;
#pragma unroll
        for (int j = 0; j < 4; j++) acc[i][j] = 0.f;
    }

    const int nkt = qt + 1;       // causal: only kv tiles <= q tile
    for (int kt = 0; kt < nkt; kt++) {
        __syncthreads();  // prior V reads done before overwrite
        // load K tile transposed: KVs[k][c] = K[c][k]
        const long bk_base = ((long)b * SS + kt * 64) * DD + head_off;
        for (int f = tid; f < 64 * 16; f += 256) {
            int c = f >> 4;
            int k4 = f & 15;
            float4 kv = *(const float4*)&Kp[bk_base + (long)c * DD + k4 * 4];
            KVs[k4 * 4 + 0][c] = kv.x;
            KVs[k4 * 4 + 1][c] = kv.y;
            KVs[k4 * 4 + 2][c] = kv.z;
            KVs[k4 * 4 + 3][c] = kv.w;
        }
        __syncthreads();

        // S = Q K^T for this 64x64 tile, 4x4 per thread
        float s[4][4];
#pragma unroll
        for (int i = 0; i < 4; i++)
#pragma unroll
            for (int j = 0; j < 4; j++) s[i][j] = 0.f;

        for (int k = 0; k < 64; k += 4) {
            float qr[4][4], kr[4][4];
#pragma unroll
            for (int i = 0; i < 4; i++) {
                float4 t = *(const float4*)&Qs[ty * 4 + i][k];
                qr[i][0] = t.x; qr[i][1] = t.y; qr[i][2] = t.z; qr[i][3] = t.w;
            }
#pragma unroll
            for (int e = 0; e < 4; e++) {
                float4 t = *(const float4*)&KVs[k + e][tx * 4];
                kr[e][0] = t.x; kr[e][1] = t.y; kr[e][2] = t.z; kr[e][3] = t.w;
            }
#pragma unroll
            for (int i = 0; i < 4; i++)
#pragma unroll
                for (int j = 0; j < 4; j++)
#pragma unroll
                    for (int e = 0; e < 4; e++)
                        s[i][j] = fmaf(qr[i][e], kr[e][j], s[i][j]);
        }

        // scale + causal mask
        const int qg0 = qt * 64 + ty * 4;
        const int kg0 = kt * 64 + tx * 4;
#pragma unroll
        for (int i = 0; i < 4; i++)
#pragma unroll
            for (int j = 0; j < 4; j++) {
                float v = s[i][j] * scale;
                s[i][j] = (kg0 + j > qg0 + i) ? -1e9f : v;
            }

        // online softmax per row (reduce over tx lanes = low 4 bits of lane)
        float corr[4];
#pragma unroll
        for (int i = 0; i < 4; i++) {
            float mt = fmaxf(fmaxf(s[i][0], s[i][1]), fmaxf(s[i][2], s[i][3]));
#pragma unroll
            for (int o = 1; o < 16; o <<= 1)
                mt = fmaxf(mt, __shfl_xor_sync(0xffffffffu, mt, o));
            float mnew = fmaxf(m[i], mt);
            corr[i] = __expf(m[i] - mnew);
            float rs = 0.f;
#pragma unroll
            for (int j = 0; j < 4; j++) {
                s[i][j] = __expf(s[i][j] - mnew);
                rs += s[i][j];
            }
#pragma unroll
            for (int o = 1; o < 16; o <<= 1)
                rs += __shfl_xor_sync(0xffffffffu, rs, o);
            l[i] = l[i] * corr[i] + rs;
            m[i] = mnew;
#pragma unroll
            for (int j = 0; j < 4; j++) acc[i][j] *= corr[i];
        }

        // write P to shared
#pragma unroll
        for (int i = 0; i < 4; i++) {
            float4 p4;
            p4.x = s[i][0]; p4.y = s[i][1]; p4.z = s[i][2]; p4.w = s[i][3];
            *(float4*)&Ps[ty * 4 + i][tx * 4] = p4;
        }
        __syncthreads();  // Ps visible; KT no longer needed

        // load V tile natural: KVs[c][d]
        const long bv_base = ((long)b * SS + kt * 64) * DD + head_off;
        for (int f = tid; f < 64 * 16; f += 256) {
            int c = f >> 4;
            int d4 = f & 15;
            *(float4*)&KVs[c][d4 * 4] = *(const float4*)&Vp[bv_base + (long)c * DD + d4 * 4];
        }
        __syncthreads();

        // acc += P * V
        for (int c = 0; c < 64; c += 4) {
            float pr[4][4], vr[4][4];
#pragma unroll
            for (int i = 0; i < 4; i++) {
                float4 t = *(const float4*)&Ps[ty * 4 + i][c];
                pr[i][0] = t.x; pr[i][1] = t.y; pr[i][2] = t.z; pr[i][3] = t.w;
            }
#pragma unroll
            for (int e = 0; e < 4; e++) {
                float4 t = *(const float4*)&KVs[c + e][tx * 4];
                vr[e][0] = t.x; vr[e][1] = t.y; vr[e][2] = t.z; vr[e][3] = t.w;
            }
#pragma unroll
            for (int i = 0; i < 4; i++)
#pragma unroll
                for (int j = 0; j < 4; j++)
#pragma unroll
                    for (int e = 0; e < 4; e++)
                        acc[i][j] = fmaf(pr[i][e], vr[e][j], acc[i][j]);
        }
    }

    // epilogue: normalize and store to AO in (B,S,D) layout
#pragma unroll
    for (int i = 0; i < 4; i++) {
        float inv = 1.0f / l[i];
        long r = (long)b * SS + qt * 64 + ty * 4 + i;
        float4 o;
        o.x = acc[i][0] * inv; o.y = acc[i][1] * inv;
        o.z = acc[i][2] * inv; o.w = acc[i][3] * inv;
        *(float4*)&AO[r * DD + head_off + tx * 4] = o;
    }
}

// ---------------- launch ---------------------------------------------------
extern "C" void kernel_launch(void* const* d_in, const int* in_sizes, int n_in,
                              void* d_out, int out_size)
{
    const float* q    = (const float*)d_in[0];
    const float* k    = (const float*)d_in[1];
    const float* v    = (const float*)d_in[2];
    // d_in[3] is the causal mask (exact tril) -> applied analytically
    const float* wq_w = (const float*)d_in[4];
    const float* wq_b = (const float*)d_in[5];
    const float* wk_w = (const float*)d_in[6];
    const float* wk_b = (const float*)d_in[7];
    const float* wv_w = (const float*)d_in[8];
    const float* wv_b = (const float*)d_in[9];
    const float* wo_w = (const float*)d_in[10];
    const float* wo_b = (const float*)d_in[11];
    float* out = (float*)d_out;

    float *pQ, *pK, *pV, *pAO;
    cudaGetSymbolAddress((void**)&pQ, g_Q);
    cudaGetSymbolAddress((void**)&pK, g_K);
    cudaGetSymbolAddress((void**)&pV, g_V);
    cudaGetSymbolAddress((void**)&pAO, g_AO);

    dim3 gb(DD / BN, MROWS / BM);   // (8, 32)
    gemm_bias_kernel<<<gb, 256>>>(q, wq_w, wq_b, pQ, MROWS, DD, DD);
    gemm_bias_kernel<<<gb, 256>>>(k, wk_w, wk_b, pK, MROWS, DD, DD);
    gemm_bias_kernel<<<gb, 256>>>(v, wv_w, wv_b, pV, MROWS, DD, DD);

    dim3 ga(SS / 64, BB * HH);      // (32, 32)
    attn_kernel<<<ga, 256>>>(pQ, pK, pV, pAO);

    gemm_bias_kernel<<<gb, 256>>>(pAO, wo_w, wo_b, out, MROWS, DD, DD);
}

// round 3
// speedup vs baseline: 3.9758x; 3.9758x over previous
#include <cuda_runtime.h>
#include <cuda_fp16.h>
#include <cstdint>
#include <cstring>

#define BBATCH 2
#define SEQ 2048
#define DMODEL 1024
#define NH 16
#define HD 64
#define MROWS (BBATCH*SEQ)

// scratch (static device globals)
__device__ __half g_Qh[MROWS * DMODEL];
__device__ __half g_Kh[MROWS * DMODEL];
__device__ __half g_Vh[MROWS * DMODEL];
__device__ float  g_AO[MROWS * DMODEL];

// ---------------- PTX helpers ---------------------------------------------
__device__ __forceinline__ uint32_t cvta_s(const void* p) {
    return (uint32_t)__cvta_generic_to_shared(p);
}
__device__ __forceinline__ void ldmx4(uint32_t* r, uint32_t a) {
    asm volatile("ldmatrix.sync.aligned.m8n8.x4.shared.b16 {%0,%1,%2,%3}, [%4];"
        : "=r"(r[0]), "=r"(r[1]), "=r"(r[2]), "=r"(r[3]) : "r"(a));
}
__device__ __forceinline__ void ldmx4t(uint32_t* r, uint32_t a) {
    asm volatile("ldmatrix.sync.aligned.m8n8.x4.trans.shared.b16 {%0,%1,%2,%3}, [%4];"
        : "=r"(r[0]), "=r"(r[1]), "=r"(r[2]), "=r"(r[3]) : "r"(a));
}
__device__ __forceinline__ void mma16816(float* d, const uint32_t* a, const uint32_t* b) {
    asm volatile("mma.sync.aligned.m16n8k16.row.col.f32.f16.f16.f32 "
        "{%0,%1,%2,%3}, {%4,%5,%6,%7}, {%8,%9}, {%0,%1,%2,%3};"
        : "+f"(d[0]), "+f"(d[1]), "+f"(d[2]), "+f"(d[3])
        : "r"(a[0]), "r"(a[1]), "r"(a[2]), "r"(a[3]), "r"(b[0]), "r"(b[1]));
}
__device__ __forceinline__ uint32_t packh2(float x, float y) {
    __half2 h = __floats2half2_rn(x, y);
    uint32_t u; memcpy(&u, &h, 4);
    return u;
}

// split a float4 into hi/lo fp16 pairs packed as uint2 (8B each)
__device__ __forceinline__ void split4(float4 v, uint2& hi, uint2& lo) {
    __half hx = __float2half_rn(v.x), hy = __float2half_rn(v.y);
    __half hz = __float2half_rn(v.z), hw = __float2half_rn(v.w);
    float lx = v.x - __half2float(hx), ly = v.y - __half2float(hy);
    float lz = v.z - __half2float(hz), lw = v.w - __half2float(hw);
    hi.x = packh2(__half2float(hx), __half2float(hy));  // exact repack
    hi.y = packh2(__half2float(hz), __half2float(hw));
    lo.x = packh2(lx, ly);
    lo.y = packh2(lz, lw);
}

// epilogue store helpers
__device__ __forceinline__ void st2(__half* C, size_t off, float a, float b) {
    __half2 h = __floats2half2_rn(a, b);
    *(__half2*)(C + off) = h;
}
__device__ __forceinline__ void st2(float* C, size_t off, float a, float b) {
    *(float2*)(C + off) = make_float2(a, b);
}

// ---------------- split-fp16 GEMM: C = A * W^T + bias ----------------------
// A (M,1024), W (N=1024,1024) both K-contiguous. Block tile 128x128, KT=32.
// smem rows: 128B = [hi(32 halves) | lo(32 halves)], SW128 xor swizzle.
template<typename OutT>
__global__ void __launch_bounds__(256) gemm_split(
    const float* __restrict__ A, const float* __restrict__ W,
    const float* __restrict__ bias, OutT* __restrict__ C)
{
    __shared__ alignas(16) char sA[128 * 128];
    __shared__ alignas(16) char sB[128 * 128];
    const uint32_t sAu = cvta_s(sA), sBu = cvta_s(sB);

    const int tid = threadIdx.x;
    const int lane = tid & 31;
    const int wid = tid >> 5;
    const int wm = wid >> 2, wn = wid & 3;      // 2 x 4 warp grid
    const int bm = blockIdx.y * 128, bn = blockIdx.x * 128;

    const int r0 = tid >> 3;     // 0..31
    const int c4 = tid & 7;      // float4 column within 32-k tile

    const float* Ap = A + (size_t)(bm + r0) * DMODEL + c4 * 4;
    const float* Wp = W + (size_t)(bn + r0) * DMODEL + c4 * 4;

    float4 ra[4], rb[4];
#pragma unroll
    for (int i = 0; i < 4; ++i) {
        ra[i] = *(const float4*)(Ap + (size_t)i * 32 * DMODEL);
        rb[i] = *(const float4*)(Wp + (size_t)i * 32 * DMODEL);
    }

    float acc[4][4][4];
#pragma unroll
    for (int mt = 0; mt < 4; ++mt)
#pragma unroll
        for (int nt = 0; nt < 4; ++nt)
#pragma unroll
            for (int e = 0; e < 4; ++e) acc[mt][nt][e] = 0.f;

    for (int it = 0; it < 32; ++it) {
        // store (possibly prefetched) regs to smem with hi/lo split
#pragma unroll
        for (int i = 0; i < 4; ++i) {
            int row = r0 + i * 32;
            int hch = (c4 >> 1) ^ (row & 7);
            int lch = ((c4 >> 1) + 4) ^ (row & 7);
            int sub = (c4 & 1) * 8;
            uint2 hi, lo;
            split4(ra[i], hi, lo);
            *(uint2*)(sA + row * 128 + hch * 16 + sub) = hi;
            *(uint2*)(sA + row * 128 + lch * 16 + sub) = lo;
            split4(rb[i], hi, lo);
            *(uint2*)(sB + row * 128 + hch * 16 + sub) = hi;
            *(uint2*)(sB + row * 128 + lch * 16 + sub) = lo;
        }
        __syncthreads();

        if (it < 31) {
            const float* Ap2 = Ap + (it + 1) * 32;
            const float* Wp2 = Wp + (it + 1) * 32;
#pragma unroll
            for (int i = 0; i < 4; ++i) {
                ra[i] = *(const float4*)(Ap2 + (size_t)i * 32 * DMODEL);
                rb[i] = *(const float4*)(Wp2 + (size_t)i * 32 * DMODEL);
            }
        }

#pragma unroll
        for (int s = 0; s < 2; ++s) {
            uint32_t ah[4][4], al[4][4];
#pragma unroll
            for (int mt = 0; mt < 4; ++mt) {
                int row = wm * 64 + mt * 16 + (lane & 15);
                int ch = s * 2 + (lane >> 4);
                ldmx4(ah[mt], sAu + row * 128 + ((ch ^ (row & 7)) * 16));
                ldmx4(al[mt], sAu + row * 128 + (((ch + 4) ^ (row & 7)) * 16));
            }
            uint32_t bh[4][2], bl[4][2];
#pragma unroll
            for (int p = 0; p < 2; ++p) {
                int g = lane >> 3;
                int nrow = wn * 32 + p * 16 + (g & 2) * 4 + (lane & 7);
                int ch = s * 2 + (g & 1);
                uint32_t t[4];
                ldmx4(t, sBu + nrow * 128 + ((ch ^ (nrow & 7)) * 16));
                bh[2 * p][0] = t[0]; bh[2 * p][1] = t[1];
                bh[2 * p + 1][0] = t[2]; bh[2 * p + 1][1] = t[3];
                ldmx4(t, sBu + nrow * 128 + (((ch + 4) ^ (nrow & 7)) * 16));
                bl[2 * p][0] = t[0]; bl[2 * p][1] = t[1];
                bl[2 * p + 1][0] = t[2]; bl[2 * p + 1][1] = t[3];
            }
#pragma unroll
            for (int mt = 0; mt < 4; ++mt)
#pragma unroll
                for (int nt = 0; nt < 4; ++nt) {
                    mma16816(acc[mt][nt], ah[mt], bh[nt]);
                    mma16816(acc[mt][nt], ah[mt], bl[nt]);
                    mma16816(acc[mt][nt], al[mt], bh[nt]);
                }
        }
        __syncthreads();
    }

    // epilogue
    const int gr = lane >> 2, ct = lane & 3;
#pragma unroll
    for (int mt = 0; mt < 4; ++mt) {
#pragma unroll
        for (int nt = 0; nt < 4; ++nt) {
            size_t row = bm + wm * 64 + mt * 16 + gr;
            int col = bn + wn * 32 + nt * 8 + ct * 2;
            float b0 = bias[col], b1 = bias[col + 1];
            st2(C, row * DMODEL + col, acc[mt][nt][0] + b0, acc[mt][nt][1] + b1);
            st2(C, (row + 8) * DMODEL + col, acc[mt][nt][2] + b0, acc[mt][nt][3] + b1);
        }
    }
}

// ---------------- fp16 flash attention (causal) -----------------------------
// grid (S/64, B*H), 128 threads (4 warps, 16 q-rows each).
__global__ void __launch_bounds__(128) attn_fp16(
    const __half* __restrict__ Q, const __half* __restrict__ K,
    const __half* __restrict__ V, float* __restrict__ AO)
{
    __shared__ alignas(16) char sK[64 * 128];
    __shared__ alignas(16) char sV[64 * 128];
    const uint32_t sKu = cvta_s(sK), sVu = cvta_s(sV);

    const int tid = threadIdx.x;
    const int lane = tid & 31;
    const int w = tid >> 5;
    const int qt = blockIdx.x;
    const int bh = blockIdx.y;
    const int b = bh >> 4, h = bh & 15;

    const size_t base = (size_t)b * SEQ * DMODEL + (size_t)h * HD;

    const int lr = tid >> 3;   // 0..15; rows lr + i*16
    const int c4 = tid & 7;

    // stage Q through sK, build register-resident Q fragments
    {
        const __half* Qp = Q + base + (size_t)(qt * 64) * DMODEL;
#pragma unroll
        for (int i = 0; i < 4; ++i) {
            int row = lr + i * 16;
            float4 v = *(const float4*)(Qp + (size_t)row * DMODEL + c4 * 8);
            *(float4*)(sK + row * 128 + ((c4 ^ (row & 7)) * 16)) = v;
        }
    }
    __syncthreads();

    uint32_t qf[4][4];
#pragma unroll
    for (int s = 0; s < 4; ++s) {
        int row = w * 16 + (lane & 15);
        int ch = 2 * s + (lane >> 4);
        ldmx4(qf[s], sKu + row * 128 + ((ch ^ (row & 7)) * 16));
    }

    float oacc[8][4];
#pragma unroll
    for (int dt = 0; dt < 8; ++dt)
#pragma unroll
        for (int e = 0; e < 4; ++e) oacc[dt][e] = 0.f;
    float m0 = -1e30f, m1 = -1e30f, l0 = 0.f, l1 = 0.f;

    const __half* Kp = K + base;
    const __half* Vp = V + base;
    float4 rk[4], rv[4];
#pragma unroll
    for (int i = 0; i < 4; ++i) {
        int row = lr + i * 16;
        rk[i] = *(const float4*)(Kp + (size_t)row * DMODEL + c4 * 8);
        rv[i] = *(const float4*)(Vp + (size_t)row * DMODEL + c4 * 8);
    }

    for (int kt = 0; kt <= qt; ++kt) {
        __syncthreads();               // prior tile's smem reads done
#pragma unroll
        for (int i = 0; i < 4; ++i) {
            int row = lr + i * 16;
            *(float4*)(sK + row * 128 + ((c4 ^ (row & 7)) * 16)) = rk[i];
            *(float4*)(sV + row * 128 + ((c4 ^ (row & 7)) * 16)) = rv[i];
        }
        __syncthreads();
        if (kt < qt) {
#pragma unroll
            for (int i = 0; i < 4; ++i) {
                int row = lr + i * 16;
                rk[i] = *(const float4*)(Kp + (size_t)((kt + 1) * 64 + row) * DMODEL + c4 * 8);
                rv[i] = *(const float4*)(Vp + (size_t)((kt + 1) * 64 + row) * DMODEL + c4 * 8);
            }
        }

        // S = Q K^T (16x64 per warp)
        float sacc[8][4];
#pragma unroll
        for (int nt = 0; nt < 8; ++nt)
#pragma unroll
            for (int e = 0; e < 4; ++e) sacc[nt][e] = 0.f;

#pragma unroll
        for (int s = 0; s < 4; ++s) {
            uint32_t kb[8][2];
#pragma unroll
            for (int p = 0; p < 4; ++p) {
                int g = lane >> 3;
                int nrow = p * 16 + (g & 2) * 4 + (lane & 7);
                int ch = 2 * s + (g & 1);
                uint32_t t[4];
                ldmx4(t, sKu + nrow * 128 + ((ch ^ (nrow & 7)) * 16));
                kb[2 * p][0] = t[0]; kb[2 * p][1] = t[1];
                kb[2 * p + 1][0] = t[2]; kb[2 * p + 1][1] = t[3];
            }
#pragma unroll
            for (int nt = 0; nt < 8; ++nt)
                mma16816(sacc[nt], qf[s], kb[nt]);
        }

        // scale + causal mask (diag tile only)
        const bool diag = (kt == qt);
        const int rq0 = w * 16 + (lane >> 2);
        const int cl0 = (lane & 3) * 2;
#pragma unroll
        for (int nt = 0; nt < 8; ++nt)
#pragma unroll
            for (int e = 0; e < 4; ++e) {
                float vv = sacc[nt][e] * 0.125f;
                if (diag) {
                    int cc = nt * 8 + cl0 + (e & 1);
                    int qq = rq0 + (e >> 1) * 8;
                    if (cc > qq) vv = -1e30f;
                }
                sacc[nt][e] = vv;
            }

        // online softmax (rows rq0 and rq0+8)
        float t0 = -1e30f, t1 = -1e30f;
#pragma unroll
        for (int nt = 0; nt < 8; ++nt) {
            t0 = fmaxf(t0, fmaxf(sacc[nt][0], sacc[nt][1]));
            t1 = fmaxf(t1, fmaxf(sacc[nt][2], sacc[nt][3]));
        }
        t0 = fmaxf(t0, __shfl_xor_sync(0xffffffffu, t0, 1));
        t0 = fmaxf(t0, __shfl_xor_sync(0xffffffffu, t0, 2));
        t1 = fmaxf(t1, __shfl_xor_sync(0xffffffffu, t1, 1));
        t1 = fmaxf(t1, __shfl_xor_sync(0xffffffffu, t1, 2));
        float mn0 = fmaxf(m0, t0), mn1 = fmaxf(m1, t1);
        float corr0 = __expf(m0 - mn0), corr1 = __expf(m1 - mn1);
        m0 = mn0; m1 = mn1;

        float rs0 = 0.f, rs1 = 0.f;
#pragma unroll
        for (int nt = 0; nt < 8; ++nt) {
            sacc[nt][0] = __expf(sacc[nt][0] - mn0);
            sacc[nt][1] = __expf(sacc[nt][1] - mn0);
            sacc[nt][2] = __expf(sacc[nt][2] - mn1);
            sacc[nt][3] = __expf(sacc[nt][3] - mn1);
            rs0 += sacc[nt][0] + sacc[nt][1];
            rs1 += sacc[nt][2] + sacc[nt][3];
        }
        rs0 += __shfl_xor_sync(0xffffffffu, rs0, 1);
        rs0 += __shfl_xor_sync(0xffffffffu, rs0, 2);
        rs1 += __shfl_xor_sync(0xffffffffu, rs1, 1);
        rs1 += __shfl_xor_sync(0xffffffffu, rs1, 2);
        l0 = l0 * corr0 + rs0;
        l1 = l1 * corr1 + rs1;
#pragma unroll
        for (int dt = 0; dt < 8; ++dt) {
            oacc[dt][0] *= corr0; oacc[dt][1] *= corr0;
            oacc[dt][2] *= corr1; oacc[dt][3] *= corr1;
        }

        // O += P V
#pragma unroll
        for (int s = 0; s < 4; ++s) {
            uint32_t af[4];
            af[0] = packh2(sacc[2 * s][0], sacc[2 * s][1]);
            af[1] = packh2(sacc[2 * s][2], sacc[2 * s][3]);
            af[2] = packh2(sacc[2 * s + 1][0], sacc[2 * s + 1][1]);
            af[3] = packh2(sacc[2 * s + 1][2], sacc[2 * s + 1][3]);
            uint32_t vb[8][2];
#pragma unroll
            for (int p = 0; p < 4; ++p) {
                int g = lane >> 3;
                int vrow = s * 16 + (g & 1) * 8 + (lane & 7);
                int ch = p * 2 + (g >> 1);
                uint32_t t[4];
                ldmx4t(t, sVu + vrow * 128 + ((ch ^ (vrow & 7)) * 16));
                vb[2 * p][0] = t[0]; vb[2 * p][1] = t[1];
                vb[2 * p + 1][0] = t[2]; vb[2 * p + 1][1] = t[3];
            }
#pragma unroll
            for (int dt = 0; dt < 8; ++dt)
                mma16816(oacc[dt], af, vb[dt]);
        }
    }

    // epilogue
    float i0 = 1.f / l0, i1 = 1.f / l1;
    const int gr = lane >> 2, ct2 = (lane & 3) * 2;
    float* Op = AO + (size_t)b * SEQ * DMODEL + (size_t)h * HD;
    size_t rowq = qt * 64 + w * 16 + gr;
#pragma unroll
    for (int dt = 0; dt < 8; ++dt) {
        int col = dt * 8 + ct2;
        *(float2*)(Op + rowq * DMODEL + col) =
            make_float2(oacc[dt][0] * i0, oacc[dt][1] * i0);
        *(float2*)(Op + (rowq + 8) * DMODEL + col) =
            make_float2(oacc[dt][2] * i1, oacc[dt][3] * i1);
    }
}

// ---------------- launch ---------------------------------------------------
extern "C" void kernel_launch(void* const* d_in, const int* in_sizes, int n_in,
                              void* d_out, int out_size)
{
    const float* q    = (const float*)d_in[0];
    const float* k    = (const float*)d_in[1];
    const float* v    = (const float*)d_in[2];
    // d_in[3]: causal mask (tril) — applied analytically
    const float* wq_w = (const float*)d_in[4];
    const float* wq_b = (const float*)d_in[5];
    const float* wk_w = (const float*)d_in[6];
    const float* wk_b = (const float*)d_in[7];
    const float* wv_w = (const float*)d_in[8];
    const float* wv_b = (const float*)d_in[9];
    const float* wo_w = (const float*)d_in[10];
    const float* wo_b = (const float*)d_in[11];
    float* out = (float*)d_out;

    __half *pQ, *pK, *pV; float* pAO;
    cudaGetSymbolAddress((void**)&pQ, g_Qh);
    cudaGetSymbolAddress((void**)&pK, g_Kh);
    cudaGetSymbolAddress((void**)&pV, g_Vh);
    cudaGetSymbolAddress((void**)&pAO, g_AO);

    dim3 gb(DMODEL / 128, MROWS / 128);   // (8, 32)
    gemm_split<__half><<<gb, 256>>>(q, wq_w, wq_b, pQ);
    gemm_split<__half><<<gb, 256>>>(k, wk_w, wk_b, pK);
    gemm_split<__half><<<gb, 256>>>(v, wv_w, wv_b, pV);

    attn_fp16<<<dim3(SEQ / 64, BBATCH * NH), 128>>>(pQ, pK, pV, pAO);

    gemm_split<float><<<gb, 256>>>(pAO, wo_w, wo_b, out);
}